// round 12
// baseline (speedup 1.0000x reference)
#include <cuda_runtime.h>
#include <cuda_bf16.h>
#include <math.h>

#define BSZ 16384
#define INF 128
#define HF  512
#define NP  288   // 32 D-logits + 256 V entries per row

// Scratch (device globals: no allocation allowed)
__device__ float g_feat[(size_t)BSZ * HF];
__device__ float g_P[(size_t)BSZ * NP];

// ---------------------------------------------------------------------------
// GEMM1: feat = relu(x[16384,128] @ W1[128,512] + b1)
// ---------------------------------------------------------------------------
#define FMA16(av, bv)                                              \
  acc[0][0] = fmaf(av.x, bv.x, acc[0][0]);                         \
  acc[0][1] = fmaf(av.x, bv.y, acc[0][1]);                         \
  acc[0][2] = fmaf(av.x, bv.z, acc[0][2]);                         \
  acc[0][3] = fmaf(av.x, bv.w, acc[0][3]);                         \
  acc[1][0] = fmaf(av.y, bv.x, acc[1][0]);                         \
  acc[1][1] = fmaf(av.y, bv.y, acc[1][1]);                         \
  acc[1][2] = fmaf(av.y, bv.z, acc[1][2]);                         \
  acc[1][3] = fmaf(av.y, bv.w, acc[1][3]);                         \
  acc[2][0] = fmaf(av.z, bv.x, acc[2][0]);                         \
  acc[2][1] = fmaf(av.z, bv.y, acc[2][1]);                         \
  acc[2][2] = fmaf(av.z, bv.z, acc[2][2]);                         \
  acc[2][3] = fmaf(av.z, bv.w, acc[2][3]);                         \
  acc[3][0] = fmaf(av.w, bv.x, acc[3][0]);                         \
  acc[3][1] = fmaf(av.w, bv.y, acc[3][1]);                         \
  acc[3][2] = fmaf(av.w, bv.z, acc[3][2]);                         \
  acc[3][3] = fmaf(av.w, bv.w, acc[3][3]);

__global__ __launch_bounds__(256) void gemm1_kernel(
    const float* __restrict__ A, const float* __restrict__ B,
    const float* __restrict__ bias) {
  __shared__ __align__(16) float As[16][64];
  __shared__ __align__(16) float Bs[16][64];
  const int tid = threadIdx.x;
  const int row0 = blockIdx.y * 64, col0 = blockIdx.x * 64;
  const int tx = tid & 15, ty = tid >> 4;
  const int am = tid >> 2, ak = (tid & 3) * 4;
  const int bk = tid >> 4, bn = (tid & 15) * 4;
  float acc[4][4];
#pragma unroll
  for (int i = 0; i < 4; i++)
#pragma unroll
    for (int j = 0; j < 4; j++) acc[i][j] = 0.f;

  for (int k0 = 0; k0 < INF; k0 += 16) {
    float4 a = *(const float4*)(A + (size_t)(row0 + am) * INF + k0 + ak);
    As[ak + 0][am] = a.x;
    As[ak + 1][am] = a.y;
    As[ak + 2][am] = a.z;
    As[ak + 3][am] = a.w;
    *(float4*)&Bs[bk][bn] =
        *(const float4*)(B + (size_t)(k0 + bk) * HF + col0 + bn);
    __syncthreads();
#pragma unroll
    for (int kk = 0; kk < 16; kk++) {
      float4 av = *(float4*)&As[kk][ty * 4];
      float4 bv = *(float4*)&Bs[kk][tx * 4];
      FMA16(av, bv);
    }
    __syncthreads();
  }
#pragma unroll
  for (int i = 0; i < 4; i++) {
    const int col = col0 + tx * 4;
    float4 o;
    o.x = fmaxf(acc[i][0] + bias[col + 0], 0.f);
    o.y = fmaxf(acc[i][1] + bias[col + 1], 0.f);
    o.z = fmaxf(acc[i][2] + bias[col + 2], 0.f);
    o.w = fmaxf(acc[i][3] + bias[col + 3], 0.f);
    *(float4*)(g_feat + (size_t)(row0 + ty * 4 + i) * HF + col) = o;
  }
}

// ---------------------------------------------------------------------------
// GEMM2: P = feat[16384,512] @ [WD|WV][512,288] + [bD|bV]
// ---------------------------------------------------------------------------
__global__ __launch_bounds__(256) void gemm2_kernel(
    const float* __restrict__ WD, const float* __restrict__ bD,
    const float* __restrict__ WV, const float* __restrict__ bV) {
  __shared__ __align__(16) float As[16][64];
  __shared__ __align__(16) float Bs[16][64];
  const int tid = threadIdx.x;
  const int row0 = blockIdx.y * 64, col0 = blockIdx.x * 64;
  const int tx = tid & 15, ty = tid >> 4;
  const int am = tid >> 2, ak = (tid & 3) * 4;
  const int bk = tid >> 4, bn = (tid & 15) * 4;
  float acc[4][4];
#pragma unroll
  for (int i = 0; i < 4; i++)
#pragma unroll
    for (int j = 0; j < 4; j++) acc[i][j] = 0.f;

  for (int k0 = 0; k0 < HF; k0 += 16) {
    float4 a = *(const float4*)(g_feat + (size_t)(row0 + am) * HF + k0 + ak);
    As[ak + 0][am] = a.x;
    As[ak + 1][am] = a.y;
    As[ak + 2][am] = a.z;
    As[ak + 3][am] = a.w;
    const int krow = k0 + bk;
#pragma unroll
    for (int q = 0; q < 4; q++) {
      const int n = col0 + bn + q;
      float w = 0.f;
      if (n < 32)
        w = WD[krow * 32 + n];
      else if (n < NP)
        w = WV[krow * 256 + (n - 32)];
      Bs[bk][bn + q] = w;
    }
    __syncthreads();
#pragma unroll
    for (int kk = 0; kk < 16; kk++) {
      float4 av = *(float4*)&As[kk][ty * 4];
      float4 bv = *(float4*)&Bs[kk][tx * 4];
      FMA16(av, bv);
    }
    __syncthreads();
  }
  const int col = col0 + tx * 4;
  if (col < NP) {
#pragma unroll
    for (int i = 0; i < 4; i++) {
      float4 o;
      o.x = acc[i][0] + (col + 0 < 32 ? bD[col + 0] : bV[col + 0 - 32]);
      o.y = acc[i][1] + (col + 1 < 32 ? bD[col + 1] : bV[col + 1 - 32]);
      o.z = acc[i][2] + (col + 2 < 32 ? bD[col + 2] : bV[col + 2 - 32]);
      o.w = acc[i][3] + (col + 3 < 32 ? bD[col + 3] : bV[col + 3 - 32]);
      *(float4*)(g_P + (size_t)(row0 + ty * 4 + i) * NP + col) = o;
    }
  }
}

// ---------------------------------------------------------------------------
// Coupled Newton–Schulz inverse sqrt: one warp per 32x32 SPD matrix.
// Lane j owns COLUMN j of Y and Z in registers. Left operands are staged in
// per-warp shared tiles and read as warp-broadcast LDS.128 (conflict-free);
// stores are lane-linear STS.32 (conflict-free). Canonical stable form:
//   T = Z*Y ; X = 1.5I - 0.5T ; Y <- Y*X ; Z <- 1.5Z - 0.5*(T*Z)
// ---------------------------------------------------------------------------
__global__ __launch_bounds__(128) void ns_kernel(float* __restrict__ out) {
  __shared__ __align__(16) float Ws[4][32][32];  // holds Y (then reused)
  __shared__ __align__(16) float Zs[4][32][32];  // holds Z, then T
  const int warp = threadIdx.x >> 5, lane = threadIdx.x & 31;
  const int b = blockIdx.x * 4 + warp;
  float(*ws)[32] = Ws[warp];
  float(*zs)[32] = Zs[warp];

  const float* p = g_P + (size_t)b * NP;

  // D = softplus(logit) + 1e-3, overflow-proof formulation
  const float dl = p[lane];
  const float D = fmaxf(dl, 0.f) + log1pf(expf(-fabsf(dl))) + 1e-3f;

  // V row for this lane (V[lane][0..7])
  float v[8];
  {
    const float4* pv = (const float4*)(p + 32);
    float4 a0 = pv[lane * 2], a1 = pv[lane * 2 + 1];
    v[0] = a0.x; v[1] = a0.y; v[2] = a0.z; v[3] = a0.w;
    v[4] = a1.x; v[5] = a1.y; v[6] = a1.z; v[7] = a1.w;
  }

  // Column j=lane of Sigma = diag(D^2) + V V^T :  y[i] = <V_i, V_lane> (+D^2 on diag)
  float y[32];
#pragma unroll
  for (int i = 0; i < 32; i++) {
    float s = 0.f;
#pragma unroll
    for (int k = 0; k < 8; k++)
      s = fmaf(__shfl_sync(0xffffffffu, v[k], i), v[k], s);
    y[i] = (i == lane) ? fmaf(D, D, s) : s;
  }

  // Frobenius norm scaling: Ahat = Sigma/||Sigma||_F has spectrum in (0,1]
  float fs = 0.f;
#pragma unroll
  for (int i = 0; i < 32; i++) fs = fmaf(y[i], y[i], fs);
#pragma unroll
  for (int o = 16; o; o >>= 1) fs += __shfl_xor_sync(0xffffffffu, fs, o);
  const float scl = sqrtf(fs);
  const float inv_s = 1.f / scl;
#pragma unroll
  for (int i = 0; i < 32; i++) y[i] *= inv_s;

  float z[32], t[32];

  // ---- iteration 0 (Z0 = I): X0 = 1.5I - 0.5*Ahat; Z1 = X0; Y1 = Ahat*X0 ----
#pragma unroll
  for (int i = 0; i < 32; i++) ws[i][lane] = y[i];   // Ws = Ahat
#pragma unroll
  for (int i = 0; i < 32; i++)
    z[i] = fmaf(-0.5f, y[i], (i == lane) ? 1.5f : 0.f);
  __syncwarp();
#pragma unroll
  for (int i = 0; i < 32; i++) {
    float acc = 0.f;
    const float4* wr = (const float4*)ws[i];
#pragma unroll
    for (int kq = 0; kq < 8; kq++) {
      float4 w = wr[kq];  // broadcast
      acc = fmaf(w.x, z[4 * kq + 0], acc);
      acc = fmaf(w.y, z[4 * kq + 1], acc);
      acc = fmaf(w.z, z[4 * kq + 2], acc);
      acc = fmaf(w.w, z[4 * kq + 3], acc);
    }
    t[i] = acc;
  }
#pragma unroll
  for (int i = 0; i < 32; i++) y[i] = t[i];

  // ---- main loop ----
#pragma unroll 1
  for (int it = 1; it < 26; ++it) {
    __syncwarp();
#pragma unroll
    for (int i = 0; i < 32; i++) {
      ws[i][lane] = y[i];
      zs[i][lane] = z[i];
    }
    __syncwarp();
    // T = Z*Y  (column j: sum_k Z[i][k]*y[k], Z broadcast from Zs)
#pragma unroll
    for (int i = 0; i < 32; i++) {
      float acc = 0.f;
      const float4* zr = (const float4*)zs[i];
#pragma unroll
      for (int kq = 0; kq < 8; kq++) {
        float4 q = zr[kq];
        acc = fmaf(q.x, y[4 * kq + 0], acc);
        acc = fmaf(q.y, y[4 * kq + 1], acc);
        acc = fmaf(q.z, y[4 * kq + 2], acc);
        acc = fmaf(q.w, y[4 * kq + 3], acc);
      }
      t[i] = acc;
    }
    // residual ||T - I||_F^2
    float r2 = 0.f;
#pragma unroll
    for (int i = 0; i < 32; i++) {
      float e = t[i] - ((i == lane) ? 1.f : 0.f);
      r2 = fmaf(e, e, r2);
    }
#pragma unroll
    for (int o = 16; o; o >>= 1) r2 += __shfl_xor_sync(0xffffffffu, r2, o);
    // stage T into Zs (Z no longer needed in smem)
    __syncwarp();
#pragma unroll
    for (int i = 0; i < 32; i++) zs[i][lane] = t[i];
    __syncwarp();
    // X = 1.5I - 0.5T (in t registers)
#pragma unroll
    for (int i = 0; i < 32; i++)
      t[i] = fmaf(-0.5f, t[i], (i == lane) ? 1.5f : 0.f);
    // Y <- Y*X : y[i] = sum_k Ws[i][k] * x[k]   (source Y is in smem -> in-place OK)
#pragma unroll
    for (int i = 0; i < 32; i++) {
      float acc = 0.f;
      const float4* wr = (const float4*)ws[i];
#pragma unroll
      for (int kq = 0; kq < 8; kq++) {
        float4 w = wr[kq];
        acc = fmaf(w.x, t[4 * kq + 0], acc);
        acc = fmaf(w.y, t[4 * kq + 1], acc);
        acc = fmaf(w.z, t[4 * kq + 2], acc);
        acc = fmaf(w.w, t[4 * kq + 3], acc);
      }
      y[i] = acc;
    }
    // u = T*Z into t (X registers are dead now; reads only Zs(T) and z)
#pragma unroll
    for (int i = 0; i < 32; i++) {
      float acc = 0.f;
      const float4* zr = (const float4*)zs[i];
#pragma unroll
      for (int kq = 0; kq < 8; kq++) {
        float4 q = zr[kq];
        acc = fmaf(q.x, z[4 * kq + 0], acc);
        acc = fmaf(q.y, z[4 * kq + 1], acc);
        acc = fmaf(q.z, z[4 * kq + 2], acc);
        acc = fmaf(q.w, z[4 * kq + 3], acc);
      }
      t[i] = acc;
    }
    // Z <- X*Z = 1.5Z - 0.5*(T*Z)
#pragma unroll
    for (int i = 0; i < 32; i++) z[i] = fmaf(-0.5f, t[i], 1.5f * z[i]);

    if (r2 < 4.0e-4f) break;  // post-update residual ~ (3/4) r^2 <= 3e-4
  }

  // out = Z / sqrt(scl); lane j writes column j -> fully coalesced
  const float oisq = rsqrtf(scl);
  float* ob = out + (size_t)b * 1024;
#pragma unroll
  for (int i = 0; i < 32; i++) ob[i * 32 + lane] = z[i] * oisq;
}

// ---------------------------------------------------------------------------
extern "C" void kernel_launch(void* const* d_in, const int* in_sizes, int n_in,
                              void* d_out, int out_size) {
  const float* x  = (const float*)d_in[0];
  const float* W1 = (const float*)d_in[1];
  const float* b1 = (const float*)d_in[2];
  const float* WD = (const float*)d_in[3];
  const float* bD = (const float*)d_in[4];
  const float* WV = (const float*)d_in[5];
  const float* bV = (const float*)d_in[6];
  float* out = (float*)d_out;

  dim3 g1(HF / 64, BSZ / 64);          // (8, 256)
  gemm1_kernel<<<g1, 256>>>(x, W1, b1);

  dim3 g2((NP + 63) / 64, BSZ / 64);   // (5, 256)
  gemm2_kernel<<<g2, 256>>>(WD, bD, WV, bV);

  ns_kernel<<<BSZ / 4, 128>>>(out);
}

// round 13
// speedup vs baseline: 1.0506x; 1.0506x over previous
#include <cuda_runtime.h>
#include <cuda_bf16.h>
#include <math.h>

#define BSZ 16384
#define INF 128
#define HF  512
#define NP  288   // 32 D-logits + 256 V entries per row

// Scratch (device globals: no allocation allowed)
__device__ float g_feat[(size_t)BSZ * HF];
__device__ float g_P[(size_t)BSZ * NP];

// ---------------------------------------------------------------------------
// GEMM1: feat = relu(x[16384,128] @ W1[128,512] + b1)
// ---------------------------------------------------------------------------
#define FMA16(av, bv)                                              \
  acc[0][0] = fmaf(av.x, bv.x, acc[0][0]);                         \
  acc[0][1] = fmaf(av.x, bv.y, acc[0][1]);                         \
  acc[0][2] = fmaf(av.x, bv.z, acc[0][2]);                         \
  acc[0][3] = fmaf(av.x, bv.w, acc[0][3]);                         \
  acc[1][0] = fmaf(av.y, bv.x, acc[1][0]);                         \
  acc[1][1] = fmaf(av.y, bv.y, acc[1][1]);                         \
  acc[1][2] = fmaf(av.y, bv.z, acc[1][2]);                         \
  acc[1][3] = fmaf(av.y, bv.w, acc[1][3]);                         \
  acc[2][0] = fmaf(av.z, bv.x, acc[2][0]);                         \
  acc[2][1] = fmaf(av.z, bv.y, acc[2][1]);                         \
  acc[2][2] = fmaf(av.z, bv.z, acc[2][2]);                         \
  acc[2][3] = fmaf(av.z, bv.w, acc[2][3]);                         \
  acc[3][0] = fmaf(av.w, bv.x, acc[3][0]);                         \
  acc[3][1] = fmaf(av.w, bv.y, acc[3][1]);                         \
  acc[3][2] = fmaf(av.w, bv.z, acc[3][2]);                         \
  acc[3][3] = fmaf(av.w, bv.w, acc[3][3]);

__global__ __launch_bounds__(256) void gemm1_kernel(
    const float* __restrict__ A, const float* __restrict__ B,
    const float* __restrict__ bias) {
  __shared__ __align__(16) float As[16][64];
  __shared__ __align__(16) float Bs[16][64];
  const int tid = threadIdx.x;
  const int row0 = blockIdx.y * 64, col0 = blockIdx.x * 64;
  const int tx = tid & 15, ty = tid >> 4;
  const int am = tid >> 2, ak = (tid & 3) * 4;
  const int bk = tid >> 4, bn = (tid & 15) * 4;
  float acc[4][4];
#pragma unroll
  for (int i = 0; i < 4; i++)
#pragma unroll
    for (int j = 0; j < 4; j++) acc[i][j] = 0.f;

  for (int k0 = 0; k0 < INF; k0 += 16) {
    float4 a = *(const float4*)(A + (size_t)(row0 + am) * INF + k0 + ak);
    As[ak + 0][am] = a.x;
    As[ak + 1][am] = a.y;
    As[ak + 2][am] = a.z;
    As[ak + 3][am] = a.w;
    *(float4*)&Bs[bk][bn] =
        *(const float4*)(B + (size_t)(k0 + bk) * HF + col0 + bn);
    __syncthreads();
#pragma unroll
    for (int kk = 0; kk < 16; kk++) {
      float4 av = *(float4*)&As[kk][ty * 4];
      float4 bv = *(float4*)&Bs[kk][tx * 4];
      FMA16(av, bv);
    }
    __syncthreads();
  }
#pragma unroll
  for (int i = 0; i < 4; i++) {
    const int col = col0 + tx * 4;
    float4 o;
    o.x = fmaxf(acc[i][0] + bias[col + 0], 0.f);
    o.y = fmaxf(acc[i][1] + bias[col + 1], 0.f);
    o.z = fmaxf(acc[i][2] + bias[col + 2], 0.f);
    o.w = fmaxf(acc[i][3] + bias[col + 3], 0.f);
    *(float4*)(g_feat + (size_t)(row0 + ty * 4 + i) * HF + col) = o;
  }
}

// ---------------------------------------------------------------------------
// GEMM2: P = feat[16384,512] @ [WD|WV][512,288] + [bD|bV]
// ---------------------------------------------------------------------------
__global__ __launch_bounds__(256) void gemm2_kernel(
    const float* __restrict__ WD, const float* __restrict__ bD,
    const float* __restrict__ WV, const float* __restrict__ bV) {
  __shared__ __align__(16) float As[16][64];
  __shared__ __align__(16) float Bs[16][64];
  const int tid = threadIdx.x;
  const int row0 = blockIdx.y * 64, col0 = blockIdx.x * 64;
  const int tx = tid & 15, ty = tid >> 4;
  const int am = tid >> 2, ak = (tid & 3) * 4;
  const int bk = tid >> 4, bn = (tid & 15) * 4;
  float acc[4][4];
#pragma unroll
  for (int i = 0; i < 4; i++)
#pragma unroll
    for (int j = 0; j < 4; j++) acc[i][j] = 0.f;

  for (int k0 = 0; k0 < HF; k0 += 16) {
    float4 a = *(const float4*)(g_feat + (size_t)(row0 + am) * HF + k0 + ak);
    As[ak + 0][am] = a.x;
    As[ak + 1][am] = a.y;
    As[ak + 2][am] = a.z;
    As[ak + 3][am] = a.w;
    const int krow = k0 + bk;
#pragma unroll
    for (int q = 0; q < 4; q++) {
      const int n = col0 + bn + q;
      float w = 0.f;
      if (n < 32)
        w = WD[krow * 32 + n];
      else if (n < NP)
        w = WV[krow * 256 + (n - 32)];
      Bs[bk][bn + q] = w;
    }
    __syncthreads();
#pragma unroll
    for (int kk = 0; kk < 16; kk++) {
      float4 av = *(float4*)&As[kk][ty * 4];
      float4 bv = *(float4*)&Bs[kk][tx * 4];
      FMA16(av, bv);
    }
    __syncthreads();
  }
  const int col = col0 + tx * 4;
  if (col < NP) {
#pragma unroll
    for (int i = 0; i < 4; i++) {
      float4 o;
      o.x = acc[i][0] + (col + 0 < 32 ? bD[col + 0] : bV[col + 0 - 32]);
      o.y = acc[i][1] + (col + 1 < 32 ? bD[col + 1] : bV[col + 1 - 32]);
      o.z = acc[i][2] + (col + 2 < 32 ? bD[col + 2] : bV[col + 2 - 32]);
      o.w = acc[i][3] + (col + 3 < 32 ? bD[col + 3] : bV[col + 3 - 32]);
      *(float4*)(g_P + (size_t)(row0 + ty * 4 + i) * NP + col) = o;
    }
  }
}

// ---------------------------------------------------------------------------
// Packed f32x2 helpers (sm_103a FFMA2 path — PTX fma.rn.f32x2)
// ---------------------------------------------------------------------------
typedef unsigned long long ull;

__device__ __forceinline__ ull ffma2(ull a, ull b, ull c) {
  ull d;
  asm("fma.rn.f32x2 %0, %1, %2, %3;" : "=l"(d) : "l"(a), "l"(b), "l"(c));
  return d;
}
__device__ __forceinline__ ull add2(ull a, ull b) {
  ull d;
  asm("add.rn.f32x2 %0, %1, %2;" : "=l"(d) : "l"(a), "l"(b));
  return d;
}
__device__ __forceinline__ ull pack2(float lo, float hi) {
  ull d;
  unsigned ul = __float_as_uint(lo), uh = __float_as_uint(hi);
  asm("mov.b64 %0, {%1, %2};" : "=l"(d) : "r"(ul), "r"(uh));
  return d;
}
__device__ __forceinline__ float hadd2(ull p) {
  unsigned lo, hi;
  asm("mov.b64 {%0, %1}, %2;" : "=r"(lo), "=r"(hi) : "l"(p));
  return __uint_as_float(lo) + __uint_as_float(hi);
}

// o[i] = sum_k M[i][k] * r[k], r pre-packed as 16 f32x2 pairs (k-major pairs).
// M rows are 128B, 16B-aligned -> LDS.128 via ulonglong2 yields packed pairs.
__device__ __forceinline__ void mm32(float* __restrict__ o,
                                     const float (*__restrict__ M)[32],
                                     const ull* __restrict__ r) {
#pragma unroll
  for (int i = 0; i < 32; i++) {
    const ulonglong2* row = (const ulonglong2*)M[i];
    ull a0 = 0ull, a1 = 0ull;  // (0.0f,0.0f) bit pattern
#pragma unroll
    for (int q = 0; q < 8; q++) {
      ulonglong2 w = row[q];
      a0 = ffma2(w.x, r[2 * q + 0], a0);
      a1 = ffma2(w.y, r[2 * q + 1], a1);
    }
    o[i] = hadd2(add2(a0, a1));
  }
}

// ---------------------------------------------------------------------------
// Coupled Newton–Schulz inverse sqrt: one warp per 32x32 SPD matrix.
// Lane j owns COLUMN j of Y and Z in registers; left operands broadcast from
// per-warp smem tiles. Canonical stable form:
//   T = Z*Y ; X = 1.5I - 0.5T ; Y <- Y*X ; Z <- 1.5Z - 0.5*(T*Z)
// ---------------------------------------------------------------------------
__global__ __launch_bounds__(128) void ns_kernel(float* __restrict__ out) {
  __shared__ __align__(16) float Ws[4][32][32];  // Y
  __shared__ __align__(16) float Zs[4][32][32];  // Z, then T
  const int warp = threadIdx.x >> 5, lane = threadIdx.x & 31;
  const int b = blockIdx.x * 4 + warp;
  float(*ws)[32] = Ws[warp];
  float(*zs)[32] = Zs[warp];

  const float* p = g_P + (size_t)b * NP;

  // D = softplus(logit) + 1e-3, overflow-proof
  const float dl = p[lane];
  const float D = fmaxf(dl, 0.f) + log1pf(expf(-fabsf(dl))) + 1e-3f;

  // V row for this lane
  float v[8];
  {
    const float4* pv = (const float4*)(p + 32);
    float4 a0 = pv[lane * 2], a1 = pv[lane * 2 + 1];
    v[0] = a0.x; v[1] = a0.y; v[2] = a0.z; v[3] = a0.w;
    v[4] = a1.x; v[5] = a1.y; v[6] = a1.z; v[7] = a1.w;
  }

  // Column j=lane of Sigma = diag(D^2) + V V^T
  float y[32];
#pragma unroll
  for (int i = 0; i < 32; i++) {
    float s = 0.f;
#pragma unroll
    for (int k = 0; k < 8; k++)
      s = fmaf(__shfl_sync(0xffffffffu, v[k], i), v[k], s);
    y[i] = (i == lane) ? fmaf(D, D, s) : s;
  }

  // Spectral scale: min(Frobenius norm, max abs-row-sum) — both >= lambda_max
  float fs = 0.f, as = 0.f;
#pragma unroll
  for (int i = 0; i < 32; i++) {
    fs = fmaf(y[i], y[i], fs);
    as += fabsf(y[i]);
  }
#pragma unroll
  for (int o = 16; o; o >>= 1) {
    fs += __shfl_xor_sync(0xffffffffu, fs, o);
    as = fmaxf(as, __shfl_xor_sync(0xffffffffu, as, o));
  }
  const float scl = fminf(sqrtf(fs), as);
  const float inv_s = 1.f / scl;
#pragma unroll
  for (int i = 0; i < 32; i++) y[i] *= inv_s;

  float z[32], t[32];
  ull p2[16];

  // ---- iteration 0 (Z0=I): X0 = 1.5I - 0.5*Ahat; Z1 = X0; Y1 = Ahat*X0 ----
#pragma unroll
  for (int i = 0; i < 32; i++) ws[i][lane] = y[i];  // Ws = Ahat
#pragma unroll
  for (int i = 0; i < 32; i++)
    z[i] = fmaf(-0.5f, y[i], (i == lane) ? 1.5f : 0.f);
#pragma unroll
  for (int q = 0; q < 16; q++) p2[q] = pack2(z[2 * q], z[2 * q + 1]);
  __syncwarp();
  mm32(y, ws, p2);  // Y1 (sources fully staged; y regs dead before write)

  // ---- main loop ----
#pragma unroll 1
  for (int it = 1; it < 26; ++it) {
    __syncwarp();
#pragma unroll
    for (int i = 0; i < 32; i++) {
      ws[i][lane] = y[i];
      zs[i][lane] = z[i];
    }
#pragma unroll
    for (int q = 0; q < 16; q++) p2[q] = pack2(y[2 * q], y[2 * q + 1]);
    __syncwarp();

    // T = Z*Y
    mm32(t, zs, p2);

    // residual ||T - I||_F^2
    float r2 = 0.f;
#pragma unroll
    for (int i = 0; i < 32; i++) {
      float e = t[i] - ((i == lane) ? 1.f : 0.f);
      r2 = fmaf(e, e, r2);
    }
#pragma unroll
    for (int o = 16; o; o >>= 1) r2 += __shfl_xor_sync(0xffffffffu, r2, o);

    // stage T into Zs (all lanes done reading old Z from Zs)
    __syncwarp();
#pragma unroll
    for (int i = 0; i < 32; i++) zs[i][lane] = t[i];
    // X = 1.5I - 0.5T, packed
#pragma unroll
    for (int i = 0; i < 32; i++)
      t[i] = fmaf(-0.5f, t[i], (i == lane) ? 1.5f : 0.f);
#pragma unroll
    for (int q = 0; q < 16; q++) p2[q] = pack2(t[2 * q], t[2 * q + 1]);
    __syncwarp();

    // Y <- Y*X   (old Y lives in Ws)
    mm32(y, ws, p2);

    // u = T*Z ; Z <- 1.5Z - 0.5u   (T lives in Zs; z packed now, X dead)
#pragma unroll
    for (int q = 0; q < 16; q++) p2[q] = pack2(z[2 * q], z[2 * q + 1]);
    mm32(t, zs, p2);
#pragma unroll
    for (int i = 0; i < 32; i++) z[i] = fmaf(-0.5f, t[i], 1.5f * z[i]);

    if (r2 < 6.0e-4f) break;  // post-update residual ~ (3/4) r^2 <= 4.5e-4
  }

  // out = Z / sqrt(scl); lane j writes column j -> fully coalesced
  const float oisq = rsqrtf(scl);
  float* ob = out + (size_t)b * 1024;
#pragma unroll
  for (int i = 0; i < 32; i++) ob[i * 32 + lane] = z[i] * oisq;
}

// ---------------------------------------------------------------------------
extern "C" void kernel_launch(void* const* d_in, const int* in_sizes, int n_in,
                              void* d_out, int out_size) {
  const float* x  = (const float*)d_in[0];
  const float* W1 = (const float*)d_in[1];
  const float* b1 = (const float*)d_in[2];
  const float* WD = (const float*)d_in[3];
  const float* bD = (const float*)d_in[4];
  const float* WV = (const float*)d_in[5];
  const float* bV = (const float*)d_in[6];
  float* out = (float*)d_out;

  dim3 g1(HF / 64, BSZ / 64);          // (8, 256)
  gemm1_kernel<<<g1, 256>>>(x, W1, b1);

  dim3 g2((NP + 63) / 64, BSZ / 64);   // (5, 256)
  gemm2_kernel<<<g2, 256>>>(WD, bD, WV, bV);

  ns_kernel<<<BSZ / 4, 128>>>(out);
}